// round 4
// baseline (speedup 1.0000x reference)
#include <cuda_runtime.h>
#include <cstddef>

// CapsuleLayer dynamic routing, recompute-u_hat strategy.
// x: [64, 2048, 8], W: [32, 2048, 16, 8], out v: [64, 32, 16] (fp32)
//
// Math restructure:
//   b starts at 0 and accumulates linearly => logits at iter k are u_hat . (v1+..+vk)
//   pass0: S1 = sum_n u_hat            (c uniform = 1/32 folded into squash)
//   pass1: c = softmax_j(u_hat . v1)        -> S2
//   pass2: c = softmax_j(u_hat . (v1+v2))   -> S3 -> v3 = output

#define B_DIM 64
#define N_DIM 2048
#define I_DIM 8
#define J_DIM 32
#define D_DIM 16

#define NC 32              // n's per block
#define BC 8               // b's per block

__device__ float g_S[3][B_DIM * J_DIM * D_DIM];   // routing-pass accumulators
__device__ float g_V1[B_DIM * J_DIM * D_DIM];     // v1
__device__ float g_V12[B_DIM * J_DIM * D_DIM];    // v1 + v2

__global__ void init_zero_kernel() {
    int i = blockIdx.x * blockDim.x + threadIdx.x;
    if (i < 3 * B_DIM * J_DIM * D_DIM) ((float*)g_S)[i] = 0.0f;
}

__device__ __forceinline__ float warp_max32(float v) {
#pragma unroll
    for (int o = 16; o; o >>= 1) v = fmaxf(v, __shfl_xor_sync(0xffffffffu, v, o));
    return v;
}
__device__ __forceinline__ float warp_sum32(float v) {
#pragma unroll
    for (int o = 16; o; o >>= 1) v += __shfl_xor_sync(0xffffffffu, v, o);
    return v;
}

// Block: 256 threads. lane = j (0..31). warp w: dh = w&1 (d-half), rep = w>>1.
// Each thread handles b0 = bbase+rep and b1 = bbase+rep+4, its j, its 8 d's.
// W[:, n, :, :] staged to smem once per n, reused by all 8 b's.
__global__ __launch_bounds__(256, 2) void pass_kernel(
    const float* __restrict__ x, const float* __restrict__ W, int pass)
{
    __shared__ float Ws[J_DIM * 132];       // row stride 132 floats (128 + pad)
    __shared__ float tb[8][2][J_DIM];       // logit partials: [warp][b-slot][j]

    const int t    = threadIdx.x;
    const int j    = t & 31;
    const int warp = t >> 5;
    const int dh   = warp & 1;              // which 8-d half
    const int rep  = warp >> 1;             // 0..3

    const int bbase  = blockIdx.y * BC;
    const int b0     = bbase + rep;
    const int b1     = bbase + rep + 4;
    const int n_base = blockIdx.x * NC;

    // v vectors for this thread's (b, j, d-half); constant over n
    float V0[8], V1r[8];
    if (pass != 0) {
        const float* Vp = (pass == 1) ? g_V1 : g_V12;
#pragma unroll
        for (int dd = 0; dd < 8; ++dd) {
            V0[dd]  = Vp[(b0 * J_DIM + j) * D_DIM + dh * 8 + dd];
            V1r[dd] = Vp[(b1 * J_DIM + j) * D_DIM + dh * 8 + dd];
        }
    }

    float acc0[8], acc1[8];
#pragma unroll
    for (int dd = 0; dd < 8; ++dd) { acc0[dd] = 0.0f; acc1[dd] = 0.0f; }

    // staging assignment: thread stages 16 floats of W row sj at offset sp*16
    const int sj = t >> 3;
    const int sp = t & 7;

    for (int nn = 0; nn < NC; ++nn) {
        const int n = n_base + nn;

        __syncthreads();   // protect Ws (and tb) from previous iteration readers
        {
            const float4* src = reinterpret_cast<const float4*>(
                W + ((size_t)sj * N_DIM + n) * (D_DIM * I_DIM) + sp * 16);
            float4* dst = reinterpret_cast<float4*>(Ws + sj * 132 + sp * 16);
            dst[0] = src[0]; dst[1] = src[1]; dst[2] = src[2]; dst[3] = src[3];
        }
        __syncthreads();

        // x vectors for (b0,n) and (b1,n): 8 floats each, warp-broadcast loads
        const float4* xp0 = reinterpret_cast<const float4*>(x + ((size_t)b0 * N_DIM + n) * I_DIM);
        const float4* xp1 = reinterpret_cast<const float4*>(x + ((size_t)b1 * N_DIM + n) * I_DIM);
        float4 xa0 = __ldg(xp0), xb0 = __ldg(xp0 + 1);
        float4 xa1 = __ldg(xp1), xb1 = __ldg(xp1 + 1);
        float xs0[8] = {xa0.x, xa0.y, xa0.z, xa0.w, xb0.x, xb0.y, xb0.z, xb0.w};
        float xs1[8] = {xa1.x, xa1.y, xa1.z, xa1.w, xb1.x, xb1.y, xb1.z, xb1.w};

        // u_hat for this thread's 8 d's, both b's (W smem read shared)
        float u0[8], u1[8];
#pragma unroll
        for (int dd = 0; dd < 8; ++dd) {
            const float4* wp = reinterpret_cast<const float4*>(
                &Ws[j * 132 + (dh * 8 + dd) * I_DIM]);
            float4 wA = wp[0], wB = wp[1];
            float a0, a1;
            a0 = wA.x * xs0[0];            a1 = wA.x * xs1[0];
            a0 = fmaf(wA.y, xs0[1], a0);   a1 = fmaf(wA.y, xs1[1], a1);
            a0 = fmaf(wA.z, xs0[2], a0);   a1 = fmaf(wA.z, xs1[2], a1);
            a0 = fmaf(wA.w, xs0[3], a0);   a1 = fmaf(wA.w, xs1[3], a1);
            a0 = fmaf(wB.x, xs0[4], a0);   a1 = fmaf(wB.x, xs1[4], a1);
            a0 = fmaf(wB.y, xs0[5], a0);   a1 = fmaf(wB.y, xs1[5], a1);
            a0 = fmaf(wB.z, xs0[6], a0);   a1 = fmaf(wB.z, xs1[6], a1);
            a0 = fmaf(wB.w, xs0[7], a0);   a1 = fmaf(wB.w, xs1[7], a1);
            u0[dd] = a0; u1[dd] = a1;
        }

        float c0 = 1.0f, c1 = 1.0f;
        if (pass != 0) {
            // logit partials over this d-half
            float tp0 = 0.0f, tp1 = 0.0f;
#pragma unroll
            for (int dd = 0; dd < 8; ++dd) {
                tp0 = fmaf(u0[dd], V0[dd], tp0);
                tp1 = fmaf(u1[dd], V1r[dd], tp1);
            }
            tb[warp][0][j] = tp0;
            tb[warp][1][j] = tp1;
            __syncthreads();
            const int pw = warp ^ 1;       // partner warp holds other d-half
            float t0 = tp0 + tb[pw][0][j];
            float t1 = tp1 + tb[pw][1][j];
            // softmax over j (= lanes)
            float m0 = warp_max32(t0);
            float m1 = warp_max32(t1);
            float e0 = __expf(t0 - m0);
            float e1 = __expf(t1 - m1);
            float z0 = warp_sum32(e0);
            float z1 = warp_sum32(e1);
            c0 = e0 / z0;
            c1 = e1 / z1;
        }

#pragma unroll
        for (int dd = 0; dd < 8; ++dd) {
            acc0[dd] = fmaf(c0, u0[dd], acc0[dd]);
            acc1[dd] = fmaf(c1, u1[dd], acc1[dd]);
        }
    }

    float* S = g_S[pass];
#pragma unroll
    for (int dd = 0; dd < 8; ++dd) {
        atomicAdd(&S[(b0 * J_DIM + j) * D_DIM + dh * 8 + dd], acc0[dd]);
        atomicAdd(&S[(b1 * J_DIM + j) * D_DIM + dh * 8 + dd], acc1[dd]);
    }
}

// squash + bookkeeping between passes. idx = (b*32 + j).
__global__ void squash_kernel(int pass, float* __restrict__ out) {
    int idx = blockIdx.x * blockDim.x + threadIdx.x;
    if (idx >= B_DIM * J_DIM) return;
    const float* S = g_S[pass];
    const float scale = (pass == 0) ? (1.0f / 32.0f) : 1.0f;
    float s[D_DIM];
    float ssq = 0.0f;
#pragma unroll
    for (int d = 0; d < D_DIM; ++d) {
        float v = S[idx * D_DIM + d] * scale;
        s[d] = v;
        ssq = fmaf(v, v, ssq);
    }
    float inv = rsqrtf(ssq + 1e-7f);
#pragma unroll
    for (int d = 0; d < D_DIM; ++d) {
        float val = s[d] * inv;
        if (pass == 0)      g_V1[idx * D_DIM + d] = val;
        else if (pass == 1) g_V12[idx * D_DIM + d] = g_V1[idx * D_DIM + d] + val;
        else                out[idx * D_DIM + d] = val;
    }
}

extern "C" void kernel_launch(void* const* d_in, const int* in_sizes, int n_in,
                              void* d_out, int out_size) {
    const float* x = (const float*)d_in[0];
    const float* W = (const float*)d_in[1];
    // robust to input ordering: x has 64*2048*8 = 1048576 elements
    if (in_sizes[0] != B_DIM * N_DIM * I_DIM) {
        x = (const float*)d_in[1];
        W = (const float*)d_in[0];
    }
    float* out = (float*)d_out;

    dim3 grid(N_DIM / NC, B_DIM / BC);   // (64, 8)

    init_zero_kernel<<<96, 1024>>>();
    pass_kernel<<<grid, 256>>>(x, W, 0);
    squash_kernel<<<8, 256>>>(0, out);
    pass_kernel<<<grid, 256>>>(x, W, 1);
    squash_kernel<<<8, 256>>>(1, out);
    pass_kernel<<<grid, 256>>>(x, W, 2);
    squash_kernel<<<2, 1024>>>(2, out);
}

// round 5
// speedup vs baseline: 1.5325x; 1.5325x over previous
#include <cuda_runtime.h>
#include <cstddef>
#include <cstdint>

// CapsuleLayer dynamic routing, recompute-u_hat strategy.
// x: [64, 2048, 8], W: [32, 2048, 16, 8], out v: [64, 32, 16] (fp32)
//
// Math restructure:
//   b starts at 0 and accumulates linearly => logits at iter k are u_hat . (v1+..+vk)
//   pass0: S1 = sum_n u_hat            (c uniform = 1/32 folded into squash)
//   pass1: c = softmax_j(u_hat . v1)        -> S2
//   pass2: c = softmax_j(u_hat . (v1+v2))   -> S3 -> v3 = output

#define B_DIM 64
#define N_DIM 2048
#define I_DIM 8
#define J_DIM 32
#define D_DIM 16

#define NC 32              // n's per block
#define BC 8               // b's per block
#define WS_STRIDE 132      // floats per W row in smem (128 + 4 pad, 16B-aligned rows)

__device__ float g_S[3][B_DIM * J_DIM * D_DIM];   // routing-pass accumulators
__device__ float g_V1[B_DIM * J_DIM * D_DIM];     // v1
__device__ float g_V12[B_DIM * J_DIM * D_DIM];    // v1 + v2

__global__ void init_zero_kernel() {
    int i = blockIdx.x * blockDim.x + threadIdx.x;
    if (i < 3 * B_DIM * J_DIM * D_DIM) ((float*)g_S)[i] = 0.0f;
}

__device__ __forceinline__ float warp_max32(float v) {
#pragma unroll
    for (int o = 16; o; o >>= 1) v = fmaxf(v, __shfl_xor_sync(0xffffffffu, v, o));
    return v;
}
__device__ __forceinline__ float warp_sum32(float v) {
#pragma unroll
    for (int o = 16; o; o >>= 1) v += __shfl_xor_sync(0xffffffffu, v, o);
    return v;
}

__device__ __forceinline__ void cp16(void* dst_smem, const void* src) {
    uint32_t d = (uint32_t)__cvta_generic_to_shared(dst_smem);
    asm volatile("cp.async.cg.shared.global [%0], [%1], 16;" :: "r"(d), "l"(src));
}
__device__ __forceinline__ void cp_commit() {
    asm volatile("cp.async.commit_group;");
}
__device__ __forceinline__ void cp_wait0() {
    asm volatile("cp.async.wait_group 0;");
}

// Block: 256 threads. lane = j (0..31). warp w: dh = w&1 (d-half), rep = w>>1.
// Each thread handles b0 = bbase+rep and b1 = bbase+rep+4, its j, its 8 d's.
// W[:, n, :, :] double-buffered in smem via cp.async; x tile staged once.
__global__ __launch_bounds__(256, 2) void pass_kernel(
    const float* __restrict__ x, const float* __restrict__ W, int pass)
{
    __shared__ float Wbuf[2][J_DIM * WS_STRIDE];   // 2 x 16.9 KB
    __shared__ float xtile[BC * NC * I_DIM];       // 8 KB : [b][n][i]
    __shared__ float tb[8][2][J_DIM];              // logit partials [warp][b-slot][j]

    const int t    = threadIdx.x;
    const int j    = t & 31;
    const int warp = t >> 5;
    const int dh   = warp & 1;              // which 8-d half
    const int rep  = warp >> 1;             // 0..3

    const int bbase  = blockIdx.y * BC;
    const int b0     = bbase + rep;
    const int b1     = bbase + rep + 4;
    const int n_base = blockIdx.x * NC;

    // ---- staging roles ----
    // W: thread stages 4 x float4 of row sj, conflict-free pattern (sp*4 + k*32 floats)
    const int sj = t >> 3;
    const int sp = t & 7;
    const float* wsrc_base = W + ((size_t)sj * N_DIM) * (D_DIM * I_DIM) + sp * 4;
    float* wdst_base = &Wbuf[0][sj * WS_STRIDE + sp * 4];

    // ---- prologue: stage x tile (whole block range) + W(n_base) as one group ----
    {
        // x tile: 512 float4s, 2 per thread. f -> b_off = f>>6, rem = f&63
        #pragma unroll
        for (int r = 0; r < 2; ++r) {
            int f = t + r * 256;
            int b_off = f >> 6;
            int rem   = f & 63;
            const float* src = x + ((size_t)(bbase + b_off) * N_DIM + n_base) * I_DIM + rem * 4;
            cp16(&xtile[b_off * (NC * I_DIM) + rem * 4], src);
        }
        // W buffer 0 for n_base
        const float* src = wsrc_base + (size_t)n_base * (D_DIM * I_DIM);
        #pragma unroll
        for (int k = 0; k < 4; ++k)
            cp16(wdst_base + k * 32, src + k * 32);
        cp_commit();
    }

    // v vectors for this thread's (b, j, d-half); constant over n
    float V0[8], V1r[8];
    if (pass != 0) {
        const float* Vp = (pass == 1) ? g_V1 : g_V12;
#pragma unroll
        for (int dd = 0; dd < 8; ++dd) {
            V0[dd]  = Vp[(b0 * J_DIM + j) * D_DIM + dh * 8 + dd];
            V1r[dd] = Vp[(b1 * J_DIM + j) * D_DIM + dh * 8 + dd];
        }
    }

    float acc0[8], acc1[8];
#pragma unroll
    for (int dd = 0; dd < 8; ++dd) { acc0[dd] = 0.0f; acc1[dd] = 0.0f; }

    const float* xrow0 = &xtile[rep * (NC * I_DIM)];
    const float* xrow1 = &xtile[(rep + 4) * (NC * I_DIM)];

    for (int nn = 0; nn < NC; ++nn) {
        const int cur = nn & 1;

        cp_wait0();          // current buffer (and, for nn==0, x tile) landed
        __syncthreads();     // visible to all warps; all warps done reading buf cur^1

        // stage next n into the other buffer (overlaps with compute below)
        if (nn + 1 < NC) {
            const float* src = wsrc_base + (size_t)(n_base + nn + 1) * (D_DIM * I_DIM);
            float* dst = wdst_base + (cur ^ 1) * (J_DIM * WS_STRIDE);
            #pragma unroll
            for (int k = 0; k < 4; ++k)
                cp16(dst + k * 32, src + k * 32);
            cp_commit();
        } else {
            cp_commit();     // keep group count uniform (empty group)
        }

        // x vectors from smem (warp-broadcast, conflict-free)
        const float4* xp0 = reinterpret_cast<const float4*>(xrow0 + nn * I_DIM);
        const float4* xp1 = reinterpret_cast<const float4*>(xrow1 + nn * I_DIM);
        float4 xa0 = xp0[0], xb0 = xp0[1];
        float4 xa1 = xp1[0], xb1 = xp1[1];
        float xs0[8] = {xa0.x, xa0.y, xa0.z, xa0.w, xb0.x, xb0.y, xb0.z, xb0.w};
        float xs1[8] = {xa1.x, xa1.y, xa1.z, xa1.w, xb1.x, xb1.y, xb1.z, xb1.w};

        // u_hat for this thread's 8 d's, both b's
        const float* Wc = &Wbuf[cur][j * WS_STRIDE + dh * 8 * I_DIM];
        float u0[8], u1[8];
#pragma unroll
        for (int dd = 0; dd < 8; ++dd) {
            const float4* wp = reinterpret_cast<const float4*>(Wc + dd * I_DIM);
            float4 wA = wp[0], wB = wp[1];
            float a0, a1;
            a0 = wA.x * xs0[0];            a1 = wA.x * xs1[0];
            a0 = fmaf(wA.y, xs0[1], a0);   a1 = fmaf(wA.y, xs1[1], a1);
            a0 = fmaf(wA.z, xs0[2], a0);   a1 = fmaf(wA.z, xs1[2], a1);
            a0 = fmaf(wA.w, xs0[3], a0);   a1 = fmaf(wA.w, xs1[3], a1);
            a0 = fmaf(wB.x, xs0[4], a0);   a1 = fmaf(wB.x, xs1[4], a1);
            a0 = fmaf(wB.y, xs0[5], a0);   a1 = fmaf(wB.y, xs1[5], a1);
            a0 = fmaf(wB.z, xs0[6], a0);   a1 = fmaf(wB.z, xs1[6], a1);
            a0 = fmaf(wB.w, xs0[7], a0);   a1 = fmaf(wB.w, xs1[7], a1);
            u0[dd] = a0; u1[dd] = a1;
        }

        float c0 = 1.0f, c1 = 1.0f;
        if (pass != 0) {
            float tp0 = 0.0f, tp1 = 0.0f;
#pragma unroll
            for (int dd = 0; dd < 8; ++dd) {
                tp0 = fmaf(u0[dd], V0[dd], tp0);
                tp1 = fmaf(u1[dd], V1r[dd], tp1);
            }
            tb[warp][0][j] = tp0;
            tb[warp][1][j] = tp1;
            // only the 2 partner warps (same rep) need to sync, not the block
            asm volatile("bar.sync %0, 64;" :: "r"(1 + rep) : "memory");
            const int pw = warp ^ 1;       // partner warp holds other d-half
            float t0 = tp0 + tb[pw][0][j];
            float t1 = tp1 + tb[pw][1][j];
            float m0 = warp_max32(t0);
            float m1 = warp_max32(t1);
            float e0 = __expf(t0 - m0);
            float e1 = __expf(t1 - m1);
            float z0 = warp_sum32(e0);
            float z1 = warp_sum32(e1);
            c0 = e0 / z0;
            c1 = e1 / z1;
        }

#pragma unroll
        for (int dd = 0; dd < 8; ++dd) {
            acc0[dd] = fmaf(c0, u0[dd], acc0[dd]);
            acc1[dd] = fmaf(c1, u1[dd], acc1[dd]);
        }
    }

    float* S = g_S[pass];
#pragma unroll
    for (int dd = 0; dd < 8; ++dd) {
        atomicAdd(&S[(b0 * J_DIM + j) * D_DIM + dh * 8 + dd], acc0[dd]);
        atomicAdd(&S[(b1 * J_DIM + j) * D_DIM + dh * 8 + dd], acc1[dd]);
    }
}

// squash + bookkeeping between passes. idx = (b*32 + j).
__global__ void squash_kernel(int pass, float* __restrict__ out) {
    int idx = blockIdx.x * blockDim.x + threadIdx.x;
    if (idx >= B_DIM * J_DIM) return;
    const float* S = g_S[pass];
    const float scale = (pass == 0) ? (1.0f / 32.0f) : 1.0f;
    float s[D_DIM];
    float ssq = 0.0f;
#pragma unroll
    for (int d = 0; d < D_DIM; ++d) {
        float v = S[idx * D_DIM + d] * scale;
        s[d] = v;
        ssq = fmaf(v, v, ssq);
    }
    float inv = rsqrtf(ssq + 1e-7f);
#pragma unroll
    for (int d = 0; d < D_DIM; ++d) {
        float val = s[d] * inv;
        if (pass == 0)      g_V1[idx * D_DIM + d] = val;
        else if (pass == 1) g_V12[idx * D_DIM + d] = g_V1[idx * D_DIM + d] + val;
        else                out[idx * D_DIM + d] = val;
    }
}

extern "C" void kernel_launch(void* const* d_in, const int* in_sizes, int n_in,
                              void* d_out, int out_size) {
    const float* x = (const float*)d_in[0];
    const float* W = (const float*)d_in[1];
    // robust to input ordering: x has 64*2048*8 = 1048576 elements
    if (in_sizes[0] != B_DIM * N_DIM * I_DIM) {
        x = (const float*)d_in[1];
        W = (const float*)d_in[0];
    }
    float* out = (float*)d_out;

    dim3 grid(N_DIM / NC, B_DIM / BC);   // (64, 8)

    init_zero_kernel<<<96, 1024>>>();
    pass_kernel<<<grid, 256>>>(x, W, 0);
    squash_kernel<<<8, 256>>>(0, out);
    pass_kernel<<<grid, 256>>>(x, W, 1);
    squash_kernel<<<8, 256>>>(1, out);
    pass_kernel<<<grid, 256>>>(x, W, 2);
    squash_kernel<<<2, 1024>>>(2, out);
}

// round 6
// speedup vs baseline: 1.7165x; 1.1201x over previous
#include <cuda_runtime.h>
#include <cstddef>
#include <cstdint>

// CapsuleLayer dynamic routing, recompute-u_hat strategy + packed f32x2 math.
// x: [64, 2048, 8], W: [32, 2048, 16, 8], out v: [64, 32, 16] (fp32)
//
// Math restructure:
//   b starts at 0 and accumulates linearly => logits at iter k are u_hat . (v1+..+vk)
//   pass0: S1 = sum_n u_hat            (c uniform = 1/32 folded into squash)
//   pass1: c = softmax_j(u_hat . v1)        -> S2
//   pass2: c = softmax_j(u_hat . (v1+v2))   -> S3 -> v3 = output
//
// W is pre-transposed once into g_Wt[j][n][i][d] so that d is innermost:
// enables fma.rn.f32x2 over d-pairs (half the FMA-pipe instructions) and a
// d-quarter warp sharding (each thread: 4 b's x 4 d's -> W smem reads halved).

#define B_DIM 64
#define N_DIM 2048
#define I_DIM 8
#define J_DIM 32
#define D_DIM 16

#define NC 32              // n's per block
#define BC 8               // b's per block
#define WS_STRIDE 132      // floats per W row in smem (128 + 4 pad)

__device__ float g_Wt[(size_t)J_DIM * N_DIM * 128];   // transposed W, [j][n][i][d]
__device__ float g_S[3][B_DIM * J_DIM * D_DIM];       // routing-pass accumulators
__device__ float g_V1[B_DIM * J_DIM * D_DIM];         // v1
__device__ float g_V12[B_DIM * J_DIM * D_DIM];        // v1 + v2

typedef unsigned long long ull;

__device__ __forceinline__ ull f2_fma(ull a, ull b, ull c) {
    ull d; asm("fma.rn.f32x2 %0, %1, %2, %3;" : "=l"(d) : "l"(a), "l"(b), "l"(c)); return d;
}
__device__ __forceinline__ ull f2_mul(ull a, ull b) {
    ull d; asm("mul.rn.f32x2 %0, %1, %2;" : "=l"(d) : "l"(a), "l"(b)); return d;
}
__device__ __forceinline__ ull f2_add(ull a, ull b) {
    ull d; asm("add.rn.f32x2 %0, %1, %2;" : "=l"(d) : "l"(a), "l"(b)); return d;
}
__device__ __forceinline__ ull f2_dup(float x) {
    ull d; asm("mov.b64 %0, {%1, %1};" : "=l"(d) : "f"(x)); return d;
}
__device__ __forceinline__ void f2_unpack(ull v, float& lo, float& hi) {
    asm("mov.b64 {%0, %1}, %2;" : "=f"(lo), "=f"(hi) : "l"(v));
}
__device__ __forceinline__ float f2_hsum(ull v) {
    float lo, hi; f2_unpack(v, lo, hi); return lo + hi;
}

__device__ __forceinline__ float warp_sum32(float v) {
#pragma unroll
    for (int o = 16; o; o >>= 1) v += __shfl_xor_sync(0xffffffffu, v, o);
    return v;
}

__device__ __forceinline__ void cp16(void* dst_smem, const void* src) {
    uint32_t d = (uint32_t)__cvta_generic_to_shared(dst_smem);
    asm volatile("cp.async.cg.shared.global [%0], [%1], 16;" :: "r"(d), "l"(src));
}
__device__ __forceinline__ void cp_commit() { asm volatile("cp.async.commit_group;"); }
__device__ __forceinline__ void cp_wait0()  { asm volatile("cp.async.wait_group 0;"); }

__global__ void init_zero_kernel() {
    int i = blockIdx.x * blockDim.x + threadIdx.x;
    if (i < 3 * B_DIM * J_DIM * D_DIM) ((float*)g_S)[i] = 0.0f;
}

// Transpose W[j][n][d][i] -> g_Wt[j][n][i][d]. 8 (j,n)-rows per block.
__global__ void transform_kernel(const float* __restrict__ W) {
    __shared__ float s[8][WS_STRIDE];
    const int t = threadIdx.x;
    const int r = t >> 5;          // row within block (warp per row)
    const int l = t & 31;
    const size_t row = (size_t)blockIdx.x * 8 + r;

    // coalesced load of one 128-float row
    const float4* src = reinterpret_cast<const float4*>(W + row * 128);
    *reinterpret_cast<float4*>(&s[r][l * 4]) = __ldg(src + l);
    __syncthreads();

    // out float4 at offset l*4 = i*16 + dq*4, with i = l>>2, dq = l&3
    const int i = l >> 2, dq = l & 3;
    float4 o;
    o.x = s[r][(dq * 4 + 0) * I_DIM + i];
    o.y = s[r][(dq * 4 + 1) * I_DIM + i];
    o.z = s[r][(dq * 4 + 2) * I_DIM + i];
    o.w = s[r][(dq * 4 + 3) * I_DIM + i];
    *reinterpret_cast<float4*>(&g_Wt[row * 128 + l * 4]) = o;
}

// Block: 256 threads. lane = j (0..31). warp w: dq = w&3 (d-quarter), rep = w>>2.
// Each thread handles 4 b's (bbase + rep*4 + bs) x 4 d's (dq*4..dq*4+3) as f32x2 pairs.
// W rows (from g_Wt) double-buffered in smem via cp.async; x tile staged once.
__global__ __launch_bounds__(256, 2) void pass_kernel(
    const float* __restrict__ x, int pass)
{
    __shared__ float Wbuf[2][J_DIM * WS_STRIDE];   // 2 x 16.9 KB
    __shared__ float xtile[BC * NC * I_DIM];       // 8 KB : [b][n][i]
    __shared__ float tb[8][4][J_DIM];              // logit partials [warp][bslot][j]

    const int t    = threadIdx.x;
    const int j    = t & 31;
    const int warp = t >> 5;
    const int dq   = warp & 3;              // d-quarter
    const int rep  = warp >> 2;             // 0..1

    const int bbase  = blockIdx.y * BC;
    const int n_base = blockIdx.x * NC;

    // W staging: thread stages row sj, conflict-free pattern (sp*4 + k*32 floats)
    const int sj = t >> 3;
    const int sp = t & 7;
    const float* wsrc_base = g_Wt + (size_t)sj * N_DIM * 128 + sp * 4;
    float* wdst_base = &Wbuf[0][sj * WS_STRIDE + sp * 4];

    // prologue: x tile + W(n_base) in one group
    #pragma unroll
    for (int r = 0; r < 2; ++r) {
        int f = t + r * 256;
        int b_off = f >> 6;
        int rem   = f & 63;
        cp16(&xtile[b_off * (NC * I_DIM) + rem * 4],
             x + ((size_t)(bbase + b_off) * N_DIM + n_base) * I_DIM + rem * 4);
    }
    {
        const float* src = wsrc_base + (size_t)n_base * 128;
        #pragma unroll
        for (int k = 0; k < 4; ++k) cp16(wdst_base + k * 32, src + k * 32);
    }
    cp_commit();

    // v (packed pairs) for this thread's 4 b's, j, d-quarter
    ull V2[4][2];
    if (pass != 0) {
        const float* Vp = (pass == 1) ? g_V1 : g_V12;
        #pragma unroll
        for (int bs = 0; bs < 4; ++bs) {
            const ull* p = reinterpret_cast<const ull*>(
                Vp + ((size_t)(bbase + rep * 4 + bs) * J_DIM + j) * D_DIM + dq * 4);
            V2[bs][0] = p[0]; V2[bs][1] = p[1];
        }
    }

    ull acc2[4][2];
    #pragma unroll
    for (int bs = 0; bs < 4; ++bs) { acc2[bs][0] = 0ull; acc2[bs][1] = 0ull; }

    for (int nn = 0; nn < NC; ++nn) {
        const int cur = nn & 1;

        cp_wait0();
        __syncthreads();

        // stage next n (overlaps compute)
        if (nn + 1 < NC) {
            const float* src = wsrc_base + (size_t)(n_base + nn + 1) * 128;
            float* dst = wdst_base + (cur ^ 1) * (J_DIM * WS_STRIDE);
            #pragma unroll
            for (int k = 0; k < 4; ++k) cp16(dst + k * 32, src + k * 32);
        }
        cp_commit();

        // x for 4 b's (broadcast smem reads)
        float xs[4][8];
        #pragma unroll
        for (int bs = 0; bs < 4; ++bs) {
            const float4* xp = reinterpret_cast<const float4*>(
                &xtile[(rep * 4 + bs) * (NC * I_DIM) + nn * I_DIM]);
            float4 a = xp[0], b = xp[1];
            xs[bs][0] = a.x; xs[bs][1] = a.y; xs[bs][2] = a.z; xs[bs][3] = a.w;
            xs[bs][4] = b.x; xs[bs][5] = b.y; xs[bs][6] = b.z; xs[bs][7] = b.w;
        }

        // u_hat (packed d-pairs): layout [i][d], this thread's quarter = dq*4..dq*4+3
        const float* Wc = &Wbuf[cur][j * WS_STRIDE + dq * 4];
        ull u2[4][2];
        {
            ulonglong2 wv = *reinterpret_cast<const ulonglong2*>(Wc);
            #pragma unroll
            for (int bs = 0; bs < 4; ++bs) {
                ull xd = f2_dup(xs[bs][0]);
                u2[bs][0] = f2_mul(wv.x, xd);
                u2[bs][1] = f2_mul(wv.y, xd);
            }
        }
        #pragma unroll
        for (int i = 1; i < 8; ++i) {
            ulonglong2 wv = *reinterpret_cast<const ulonglong2*>(Wc + i * 16);
            #pragma unroll
            for (int bs = 0; bs < 4; ++bs) {
                ull xd = f2_dup(xs[bs][i]);
                u2[bs][0] = f2_fma(wv.x, xd, u2[bs][0]);
                u2[bs][1] = f2_fma(wv.y, xd, u2[bs][1]);
            }
        }

        if (pass != 0) {
            // logit partial over this d-quarter
            #pragma unroll
            for (int bs = 0; bs < 4; ++bs)
                tb[warp][bs][j] = f2_hsum(f2_fma(u2[bs][0], V2[bs][0],
                                                 f2_mul(u2[bs][1], V2[bs][1])));
            asm volatile("bar.sync %0, 128;" :: "r"(1 + rep) : "memory");
            const int wg = rep * 4;
            #pragma unroll
            for (int bs = 0; bs < 4; ++bs) {
                float tt = tb[wg][bs][j] + tb[wg + 1][bs][j]
                         + tb[wg + 2][bs][j] + tb[wg + 3][bs][j];
                // logits are O(1): softmax without max-subtraction is safe here
                float e = __expf(tt);
                float z = warp_sum32(e);
                ull c2 = f2_dup(__fdividef(e, z));
                acc2[bs][0] = f2_fma(c2, u2[bs][0], acc2[bs][0]);
                acc2[bs][1] = f2_fma(c2, u2[bs][1], acc2[bs][1]);
            }
        } else {
            #pragma unroll
            for (int bs = 0; bs < 4; ++bs) {
                acc2[bs][0] = f2_add(acc2[bs][0], u2[bs][0]);
                acc2[bs][1] = f2_add(acc2[bs][1], u2[bs][1]);
            }
        }
    }

    float* S = g_S[pass];
    #pragma unroll
    for (int bs = 0; bs < 4; ++bs) {
        float* dst = &S[((size_t)(bbase + rep * 4 + bs) * J_DIM + j) * D_DIM + dq * 4];
        float a, b, c, d;
        f2_unpack(acc2[bs][0], a, b);
        f2_unpack(acc2[bs][1], c, d);
        atomicAdd(dst + 0, a);
        atomicAdd(dst + 1, b);
        atomicAdd(dst + 2, c);
        atomicAdd(dst + 3, d);
    }
}

// squash + bookkeeping between passes. idx = (b*32 + j).
__global__ void squash_kernel(int pass, float* __restrict__ out) {
    int idx = blockIdx.x * blockDim.x + threadIdx.x;
    if (idx >= B_DIM * J_DIM) return;
    const float* S = g_S[pass];
    const float scale = (pass == 0) ? (1.0f / 32.0f) : 1.0f;
    float s[D_DIM];
    float ssq = 0.0f;
#pragma unroll
    for (int d = 0; d < D_DIM; ++d) {
        float v = S[idx * D_DIM + d] * scale;
        s[d] = v;
        ssq = fmaf(v, v, ssq);
    }
    float inv = rsqrtf(ssq + 1e-7f);
#pragma unroll
    for (int d = 0; d < D_DIM; ++d) {
        float val = s[d] * inv;
        if (pass == 0)      g_V1[idx * D_DIM + d] = val;
        else if (pass == 1) g_V12[idx * D_DIM + d] = g_V1[idx * D_DIM + d] + val;
        else                out[idx * D_DIM + d] = val;
    }
}

extern "C" void kernel_launch(void* const* d_in, const int* in_sizes, int n_in,
                              void* d_out, int out_size) {
    const float* x = (const float*)d_in[0];
    const float* W = (const float*)d_in[1];
    // robust to input ordering: x has 64*2048*8 = 1048576 elements
    if (in_sizes[0] != B_DIM * N_DIM * I_DIM) {
        x = (const float*)d_in[1];
        W = (const float*)d_in[0];
    }
    float* out = (float*)d_out;

    dim3 grid(N_DIM / NC, B_DIM / BC);   // (64, 8)

    init_zero_kernel<<<96, 1024>>>();
    transform_kernel<<<(J_DIM * N_DIM) / 8, 256>>>(W);
    pass_kernel<<<grid, 256>>>(x, 0);
    squash_kernel<<<8, 256>>>(0, out);
    pass_kernel<<<grid, 256>>>(x, 1);
    squash_kernel<<<8, 256>>>(1, out);
    pass_kernel<<<grid, 256>>>(x, 2);
    squash_kernel<<<2, 1024>>>(2, out);
}